// round 1
// baseline (speedup 1.0000x reference)
#include <cuda_runtime.h>
#include <cuda_bf16.h>
#include <cstdint>

#define NFACT 100000
#define NCOMP 10000
#define NEDGE 800000
#define DFACT 768
#define HID   128
#define NB    256

// ---------------- scratch (device globals; no allocation allowed) ----------
__device__ float g_wfc[NEDGE];
__device__ float g_wcf[NEDGE];
__device__ float g_dfc_s[NFACT];   // deg of fc_src over facts   -> inv-sqrt in place
__device__ float g_dfc_d[NCOMP];   // deg of fc_dst over companies
__device__ float g_dcf_s[NCOMP];   // deg of cf_src over companies
__device__ float g_dcf_d[NFACT];   // deg of cf_dst over facts
__device__ float g_H1[(size_t)NFACT * HID];   // x_fact @ W1_fc
__device__ float g_c1[(size_t)NCOMP * HID];   // aggregated -> relu(+b1)
__device__ float g_H2[(size_t)NCOMP * HID];   // c1 @ W2_cf
__device__ float g_f2[(size_t)NFACT * HID];   // aggregated (pre-relu/bias)
__device__ float g_psum[NB];
__device__ float g_pcnt[NB];

// ---------------- kernels --------------------------------------------------

// per-edge learned gate + degree accumulation (both endpoints)
__global__ void gate_deg_kernel(const float* __restrict__ ea,
                                const int* __restrict__ src,
                                const int* __restrict__ dst,
                                const float* __restrict__ Wm,
                                const float* __restrict__ bm,
                                float* __restrict__ w,
                                float* __restrict__ deg_s,
                                float* __restrict__ deg_d,
                                int E) {
    int e = blockIdx.x * blockDim.x + threadIdx.x;
    if (e >= E) return;
    float a0 = ea[2 * e + 0];
    float a1 = ea[2 * e + 1];
    float z  = a0 * Wm[0] + a1 * Wm[1] + bm[0];
    float ww = 1.f / (1.f + expf(-z));
    w[e] = ww;
    atomicAdd(&deg_s[src[e]], ww);
    atomicAdd(&deg_d[dst[e]], ww);
}

__global__ void invsqrt_kernel(float* __restrict__ d, int n) {
    int i = blockIdx.x * blockDim.x + threadIdx.x;
    if (i >= n) return;
    float v = d[i];
    d[i] = (v > 0.f) ? rsqrtf(v) : 0.f;
}

// C[M,128] = A[M,K] @ B[K,128]   (K % 16 == 0). Classic tiled SGEMM,
// BM=64, BN=128, BK=16, 256 thr, 8x4 micro-tile.
__global__ __launch_bounds__(256) void sgemm128_kernel(
        const float* __restrict__ A, const float* __restrict__ Bw,
        float* __restrict__ C, int M, int K) {
    __shared__ float As[16][68];   // [k][row], padded
    __shared__ float Bs[16][128];  // [k][col]

    const int tid  = threadIdx.x;
    const int row0 = blockIdx.x * 64;
    const int ty   = tid >> 5;    // 0..7  -> rows ty*8..ty*8+7
    const int tx   = tid & 31;    // 0..31 -> cols tx*4..tx*4+3

    const int ar   = tid >> 2;          // 0..63
    const int ac   = (tid & 3) << 2;    // 0,4,8,12
    const int arow = row0 + ar;

    float acc[8][4] = {};

    for (int k0 = 0; k0 < K; k0 += 16) {
        float4 av = make_float4(0.f, 0.f, 0.f, 0.f);
        if (arow < M)
            av = *reinterpret_cast<const float4*>(A + (size_t)arow * K + k0 + ac);
        As[ac + 0][ar] = av.x; As[ac + 1][ar] = av.y;
        As[ac + 2][ar] = av.z; As[ac + 3][ar] = av.w;

#pragma unroll
        for (int i = 0; i < 2; i++) {
            int lin = tid + i * 256;           // float4 index in 16x32 grid
            int br  = lin >> 5;
            int bc4 = (lin & 31) << 2;
            float4 bv = *reinterpret_cast<const float4*>(
                Bw + (size_t)(k0 + br) * 128 + bc4);
            Bs[br][bc4 + 0] = bv.x; Bs[br][bc4 + 1] = bv.y;
            Bs[br][bc4 + 2] = bv.z; Bs[br][bc4 + 3] = bv.w;
        }
        __syncthreads();

#pragma unroll
        for (int kk = 0; kk < 16; kk++) {
            float a[8], b[4];
#pragma unroll
            for (int m = 0; m < 8; m++) a[m] = As[kk][ty * 8 + m];
#pragma unroll
            for (int n = 0; n < 4; n++) b[n] = Bs[kk][tx * 4 + n];
#pragma unroll
            for (int m = 0; m < 8; m++)
#pragma unroll
                for (int n = 0; n < 4; n++) acc[m][n] += a[m] * b[n];
        }
        __syncthreads();
    }

#pragma unroll
    for (int m = 0; m < 8; m++) {
        int r = row0 + ty * 8 + m;
        if (r < M) {
            float4 o = make_float4(acc[m][0], acc[m][1], acc[m][2], acc[m][3]);
            *reinterpret_cast<float4*>(C + (size_t)r * 128 + tx * 4) = o;
        }
    }
}

// one warp per edge: out[dst] += norm_e * h[src]  (128 floats, v4 reduction)
__global__ void agg128_kernel(float* __restrict__ out,
                              const float* __restrict__ h,
                              const int* __restrict__ src,
                              const int* __restrict__ dst,
                              const float* __restrict__ w,
                              const float* __restrict__ dis_s,
                              const float* __restrict__ dis_d,
                              int E) {
    int e = blockIdx.x * (blockDim.x >> 5) + (threadIdx.x >> 5);
    if (e >= E) return;
    int lane = threadIdx.x & 31;
    int s = src[e], d = dst[e];
    float nrm = w[e] * dis_s[s] * dis_d[d];
    float4 v = reinterpret_cast<const float4*>(h + (size_t)s * 128)[lane];
    float* op = out + (size_t)d * 128 + lane * 4;
    asm volatile("red.global.add.v4.f32 [%0], {%1,%2,%3,%4};"
                 :: "l"(op), "f"(nrm * v.x), "f"(nrm * v.y),
                    "f"(nrm * v.z), "f"(nrm * v.w)
                 : "memory");
}

__global__ void bias_relu_kernel(float* __restrict__ x,
                                 const float* __restrict__ b, int n) {
    int i = blockIdx.x * blockDim.x + threadIdx.x;
    if (i >= n) return;
    x[i] = fmaxf(x[i] + b[i & (HID - 1)], 0.f);
}

// fused: relu(f2+b2) . Wc per fact node, atomically pooled per graph
__global__ void pool_kernel(const float* __restrict__ f2,
                            const float* __restrict__ b2,
                            const float* __restrict__ Wc,
                            const int* __restrict__ batch,
                            float* __restrict__ psum,
                            float* __restrict__ pcnt, int n) {
    int node = blockIdx.x * (blockDim.x >> 5) + (threadIdx.x >> 5);
    if (node >= n) return;
    int lane = threadIdx.x & 31;
    float4 v  = reinterpret_cast<const float4*>(f2 + (size_t)node * 128)[lane];
    float4 bb = reinterpret_cast<const float4*>(b2)[lane];
    float4 wc = reinterpret_cast<const float4*>(Wc)[lane];
    float s = fmaxf(v.x + bb.x, 0.f) * wc.x + fmaxf(v.y + bb.y, 0.f) * wc.y +
              fmaxf(v.z + bb.z, 0.f) * wc.z + fmaxf(v.w + bb.w, 0.f) * wc.w;
#pragma unroll
    for (int o = 16; o; o >>= 1) s += __shfl_down_sync(0xffffffffu, s, o);
    if (lane == 0) {
        int g = batch[node];
        atomicAdd(&psum[g], s);
        atomicAdd(&pcnt[g], 1.f);
    }
}

__global__ void final_kernel(const float* __restrict__ psum,
                             const float* __restrict__ pcnt,
                             const float* __restrict__ bc,
                             float* __restrict__ out) {
    int g = threadIdx.x;
    if (g < NB) out[g] = psum[g] / fmaxf(pcnt[g], 1.f) + bc[0];
}

// ---------------- launch ---------------------------------------------------
extern "C" void kernel_launch(void* const* d_in, const int* in_sizes, int n_in,
                              void* d_out, int out_size) {
    const float* x_fact     = (const float*)d_in[0];
    const float* ea_fc      = (const float*)d_in[2];
    const float* ea_cf      = (const float*)d_in[3];
    const int*   fc_src     = (const int*)d_in[4];
    const int*   fc_dst     = (const int*)d_in[5];
    const int*   cf_src     = (const int*)d_in[6];
    const int*   cf_dst     = (const int*)d_in[7];
    const int*   batch_fact = (const int*)d_in[8];
    const float* Wm         = (const float*)d_in[9];
    const float* bm         = (const float*)d_in[10];
    const float* W1_fc      = (const float*)d_in[11];
    const float* b1_fc      = (const float*)d_in[12];
    const float* W2_cf      = (const float*)d_in[17];
    const float* b2_cf      = (const float*)d_in[18];
    const float* Wc         = (const float*)d_in[19];
    const float* bc         = (const float*)d_in[20];
    float* out = (float*)d_out;

    float *wfc, *wcf, *dfcs, *dfcd, *dcfs, *dcfd, *H1, *c1, *H2, *f2, *psum, *pcnt;
    cudaGetSymbolAddress((void**)&wfc,  g_wfc);
    cudaGetSymbolAddress((void**)&wcf,  g_wcf);
    cudaGetSymbolAddress((void**)&dfcs, g_dfc_s);
    cudaGetSymbolAddress((void**)&dfcd, g_dfc_d);
    cudaGetSymbolAddress((void**)&dcfs, g_dcf_s);
    cudaGetSymbolAddress((void**)&dcfd, g_dcf_d);
    cudaGetSymbolAddress((void**)&H1,   g_H1);
    cudaGetSymbolAddress((void**)&c1,   g_c1);
    cudaGetSymbolAddress((void**)&H2,   g_H2);
    cudaGetSymbolAddress((void**)&f2,   g_f2);
    cudaGetSymbolAddress((void**)&psum, g_psum);
    cudaGetSymbolAddress((void**)&pcnt, g_pcnt);

    // zero accumulators (memset nodes are graph-capturable)
    cudaMemsetAsync(dfcs, 0, NFACT * sizeof(float));
    cudaMemsetAsync(dfcd, 0, NCOMP * sizeof(float));
    cudaMemsetAsync(dcfs, 0, NCOMP * sizeof(float));
    cudaMemsetAsync(dcfd, 0, NFACT * sizeof(float));
    cudaMemsetAsync(c1,   0, (size_t)NCOMP * HID * sizeof(float));
    cudaMemsetAsync(f2,   0, (size_t)NFACT * HID * sizeof(float));
    cudaMemsetAsync(psum, 0, NB * sizeof(float));
    cudaMemsetAsync(pcnt, 0, NB * sizeof(float));

    // edge gates + degrees (both relations)
    gate_deg_kernel<<<(NEDGE + 255) / 256, 256>>>(ea_fc, fc_src, fc_dst, Wm, bm,
                                                  wfc, dfcs, dfcd, NEDGE);
    gate_deg_kernel<<<(NEDGE + 255) / 256, 256>>>(ea_cf, cf_src, cf_dst, Wm, bm,
                                                  wcf, dcfs, dcfd, NEDGE);
    invsqrt_kernel<<<(NFACT + 255) / 256, 256>>>(dfcs, NFACT);
    invsqrt_kernel<<<(NCOMP + 255) / 256, 256>>>(dfcd, NCOMP);
    invsqrt_kernel<<<(NCOMP + 255) / 256, 256>>>(dcfs, NCOMP);
    invsqrt_kernel<<<(NFACT + 255) / 256, 256>>>(dcfd, NFACT);

    // layer 1 (only fact->company branch feeds the output)
    sgemm128_kernel<<<(NFACT + 63) / 64, 256>>>(x_fact, W1_fc, H1, NFACT, DFACT);
    agg128_kernel<<<(NEDGE + 7) / 8, 256>>>(c1, H1, fc_src, fc_dst,
                                            wfc, dfcs, dfcd, NEDGE);
    bias_relu_kernel<<<(NCOMP * HID + 255) / 256, 256>>>(c1, b1_fc, NCOMP * HID);

    // layer 2 (company->fact branch)
    sgemm128_kernel<<<(NCOMP + 63) / 64, 256>>>(c1, W2_cf, H2, NCOMP, HID);
    agg128_kernel<<<(NEDGE + 7) / 8, 256>>>(f2, H2, cf_src, cf_dst,
                                            wcf, dcfs, dcfd, NEDGE);

    // fused relu+bias+classifier-dot+mean-pool
    pool_kernel<<<(NFACT + 7) / 8, 256>>>(f2, b2_cf, Wc, batch_fact,
                                          psum, pcnt, NFACT);
    final_kernel<<<1, NB>>>(psum, pcnt, bc, out);
}

// round 2
// speedup vs baseline: 1.4744x; 1.4744x over previous
#include <cuda_runtime.h>
#include <cuda_bf16.h>
#include <cstdint>

#define NFACT 100000
#define NCOMP 10000
#define NEDGE 800000
#define DFACT 768
#define HID   128
#define NB    256

// ---------------- scratch (device globals; no allocation allowed) ----------
__device__ float g_wfc[NEDGE];
__device__ float g_wcf[NEDGE];
__device__ float g_dfc_s[NFACT];
__device__ float g_dfc_d[NCOMP];
__device__ float g_dcf_s[NCOMP];
__device__ float g_dcf_d[NFACT];
__device__ float g_H1[(size_t)NFACT * HID];
__device__ float g_c1[(size_t)NCOMP * HID];   // pre-activation (bias+relu fused into GEMM2 A-load)
__device__ float g_H2[(size_t)NCOMP * HID];
__device__ float g_f2[(size_t)NFACT * HID];
__device__ float g_psum[NB];
__device__ float g_pcnt[NB];

// ---------------- helpers --------------------------------------------------
__device__ __forceinline__ uint32_t f2tf32(float x) {
    uint32_t r;
    asm("cvt.rna.tf32.f32 %0, %1;" : "=r"(r) : "f"(x));
    return r;
}

__device__ __forceinline__ void mma_tf32(float* c, const uint32_t* a, const uint32_t* b) {
    asm volatile(
        "mma.sync.aligned.m16n8k8.row.col.f32.tf32.tf32.f32 "
        "{%0,%1,%2,%3}, {%4,%5,%6,%7}, {%8,%9}, {%0,%1,%2,%3};"
        : "+f"(c[0]), "+f"(c[1]), "+f"(c[2]), "+f"(c[3])
        : "r"(a[0]), "r"(a[1]), "r"(a[2]), "r"(a[3]), "r"(b[0]), "r"(b[1]));
}

// ---------------- kernels --------------------------------------------------

__global__ void gate_deg_kernel(const float* __restrict__ ea,
                                const int* __restrict__ src,
                                const int* __restrict__ dst,
                                const float* __restrict__ Wm,
                                const float* __restrict__ bm,
                                float* __restrict__ w,
                                float* __restrict__ deg_s,
                                float* __restrict__ deg_d,
                                int E) {
    int e = blockIdx.x * blockDim.x + threadIdx.x;
    if (e >= E) return;
    float a0 = ea[2 * e + 0];
    float a1 = ea[2 * e + 1];
    float z  = a0 * Wm[0] + a1 * Wm[1] + bm[0];
    float ww = 1.f / (1.f + expf(-z));
    w[e] = ww;
    atomicAdd(&deg_s[src[e]], ww);
    atomicAdd(&deg_d[dst[e]], ww);
}

__global__ void invsqrt_kernel(float* __restrict__ d, int n) {
    int i = blockIdx.x * blockDim.x + threadIdx.x;
    if (i >= n) return;
    float v = d[i];
    d[i] = (v > 0.f) ? rsqrtf(v) : 0.f;
}

// C[M,128] = act(A[M,K]) @ B[K,128], tf32 tensor-core GEMM.
// act(A) = relu(A + abias[k]) when abias != nullptr, else identity.
// BM=128, BN=128, BK=16, 256 threads (8 warps, warp tile 32x64), double-buffered.
__global__ __launch_bounds__(256) void mma_gemm128_kernel(
        const float* __restrict__ A, const float* __restrict__ Bw,
        const float* __restrict__ abias, float* __restrict__ C,
        int M, int K) {
    __shared__ uint32_t As[2][128][20];   // [buf][row][k], pad 20 -> conflict-free frags
    __shared__ uint32_t Bs[2][16][132];   // [buf][k][col], pad 132

    const int tid  = threadIdx.x;
    const int wid  = tid >> 5;
    const int lane = tid & 31;
    const int gid  = lane >> 2;
    const int tid4 = lane & 3;
    const int wm   = (wid & 3) * 32;     // warp M offset in tile
    const int wn   = (wid >> 2) * 64;    // warp N offset in tile
    const int row0 = blockIdx.x * 128;
    const int ntiles = K / 16;

    // per-thread staging indices
    int aRow[2], aCol[2], bKr[2], bCol[2];
#pragma unroll
    for (int i = 0; i < 2; i++) {
        int idx = tid + i * 256;
        aRow[i] = idx >> 2;  aCol[i] = (idx & 3) << 2;
        bKr[i]  = idx >> 5;  bCol[i] = (idx & 31) << 2;
    }

    float acc[2][8][4];
#pragma unroll
    for (int mi = 0; mi < 2; mi++)
#pragma unroll
        for (int ni = 0; ni < 8; ni++)
#pragma unroll
            for (int j = 0; j < 4; j++) acc[mi][ni][j] = 0.f;

    float4 aReg[2], bReg[2];

#define LOAD_TILE(t)                                                          \
    do {                                                                      \
        int k0 = (t) * 16;                                                    \
        _Pragma("unroll")                                                     \
        for (int i = 0; i < 2; i++) {                                         \
            int r = row0 + aRow[i];                                           \
            aReg[i] = (r < M)                                                 \
                ? *reinterpret_cast<const float4*>(A + (size_t)r * K + k0 + aCol[i]) \
                : make_float4(0.f, 0.f, 0.f, 0.f);                            \
        }                                                                     \
        _Pragma("unroll")                                                     \
        for (int i = 0; i < 2; i++)                                           \
            bReg[i] = *reinterpret_cast<const float4*>(                       \
                Bw + (size_t)(k0 + bKr[i]) * 128 + bCol[i]);                  \
    } while (0)

#define STORE_TILE(bf, t)                                                     \
    do {                                                                      \
        int k0 = (t) * 16;                                                    \
        _Pragma("unroll")                                                     \
        for (int i = 0; i < 2; i++) {                                         \
            float4 v = aReg[i];                                               \
            if (abias) {                                                      \
                v.x = fmaxf(v.x + abias[k0 + aCol[i] + 0], 0.f);              \
                v.y = fmaxf(v.y + abias[k0 + aCol[i] + 1], 0.f);              \
                v.z = fmaxf(v.z + abias[k0 + aCol[i] + 2], 0.f);              \
                v.w = fmaxf(v.w + abias[k0 + aCol[i] + 3], 0.f);              \
            }                                                                 \
            As[bf][aRow[i]][aCol[i] + 0] = f2tf32(v.x);                       \
            As[bf][aRow[i]][aCol[i] + 1] = f2tf32(v.y);                       \
            As[bf][aRow[i]][aCol[i] + 2] = f2tf32(v.z);                       \
            As[bf][aRow[i]][aCol[i] + 3] = f2tf32(v.w);                       \
        }                                                                     \
        _Pragma("unroll")                                                     \
        for (int i = 0; i < 2; i++) {                                         \
            float4 v = bReg[i];                                               \
            Bs[bf][bKr[i]][bCol[i] + 0] = f2tf32(v.x);                        \
            Bs[bf][bKr[i]][bCol[i] + 1] = f2tf32(v.y);                        \
            Bs[bf][bKr[i]][bCol[i] + 2] = f2tf32(v.z);                        \
            Bs[bf][bKr[i]][bCol[i] + 3] = f2tf32(v.w);                        \
        }                                                                     \
    } while (0)

#define COMPUTE(bf)                                                           \
    do {                                                                      \
        _Pragma("unroll")                                                     \
        for (int kk = 0; kk < 16; kk += 8) {                                  \
            uint32_t afr[2][4], bfr[8][2];                                    \
            _Pragma("unroll")                                                 \
            for (int mi = 0; mi < 2; mi++) {                                  \
                int r = wm + mi * 16;                                         \
                afr[mi][0] = As[bf][r + gid][kk + tid4];                      \
                afr[mi][1] = As[bf][r + gid + 8][kk + tid4];                  \
                afr[mi][2] = As[bf][r + gid][kk + tid4 + 4];                  \
                afr[mi][3] = As[bf][r + gid + 8][kk + tid4 + 4];              \
            }                                                                 \
            _Pragma("unroll")                                                 \
            for (int ni = 0; ni < 8; ni++) {                                  \
                int c = wn + ni * 8 + gid;                                    \
                bfr[ni][0] = Bs[bf][kk + tid4][c];                            \
                bfr[ni][1] = Bs[bf][kk + tid4 + 4][c];                        \
            }                                                                 \
            _Pragma("unroll")                                                 \
            for (int mi = 0; mi < 2; mi++)                                    \
                _Pragma("unroll")                                             \
                for (int ni = 0; ni < 8; ni++)                                \
                    mma_tf32(acc[mi][ni], afr[mi], bfr[ni]);                  \
        }                                                                     \
    } while (0)

    LOAD_TILE(0);
    STORE_TILE(0, 0);
    __syncthreads();

    int buf = 0;
    for (int t = 0; t < ntiles; t++) {
        if (t + 1 < ntiles) LOAD_TILE(t + 1);
        COMPUTE(buf);
        if (t + 1 < ntiles) {
            STORE_TILE(buf ^ 1, t + 1);
            __syncthreads();
            buf ^= 1;
        }
    }

#pragma unroll
    for (int mi = 0; mi < 2; mi++)
#pragma unroll
        for (int ni = 0; ni < 8; ni++) {
            int r1 = row0 + wm + mi * 16 + gid;
            int r2 = r1 + 8;
            int c  = wn + ni * 8 + tid4 * 2;
            if (r1 < M)
                *reinterpret_cast<float2*>(C + (size_t)r1 * 128 + c) =
                    make_float2(acc[mi][ni][0], acc[mi][ni][1]);
            if (r2 < M)
                *reinterpret_cast<float2*>(C + (size_t)r2 * 128 + c) =
                    make_float2(acc[mi][ni][2], acc[mi][ni][3]);
        }
#undef LOAD_TILE
#undef STORE_TILE
#undef COMPUTE
}

// one warp per edge: out[dst] += norm_e * h[src]  (128 floats, v4 reduction)
__global__ void agg128_kernel(float* __restrict__ out,
                              const float* __restrict__ h,
                              const int* __restrict__ src,
                              const int* __restrict__ dst,
                              const float* __restrict__ w,
                              const float* __restrict__ dis_s,
                              const float* __restrict__ dis_d,
                              int E) {
    int e = blockIdx.x * (blockDim.x >> 5) + (threadIdx.x >> 5);
    if (e >= E) return;
    int lane = threadIdx.x & 31;
    int s = src[e], d = dst[e];
    float nrm = w[e] * dis_s[s] * dis_d[d];
    float4 v = reinterpret_cast<const float4*>(h + (size_t)s * 128)[lane];
    float* op = out + (size_t)d * 128 + lane * 4;
    asm volatile("red.global.add.v4.f32 [%0], {%1,%2,%3,%4};"
                 :: "l"(op), "f"(nrm * v.x), "f"(nrm * v.y),
                    "f"(nrm * v.z), "f"(nrm * v.w)
                 : "memory");
}

// fused: relu(f2+b2) . Wc per fact node, atomically pooled per graph
__global__ void pool_kernel(const float* __restrict__ f2,
                            const float* __restrict__ b2,
                            const float* __restrict__ Wc,
                            const int* __restrict__ batch,
                            float* __restrict__ psum,
                            float* __restrict__ pcnt, int n) {
    int node = blockIdx.x * (blockDim.x >> 5) + (threadIdx.x >> 5);
    if (node >= n) return;
    int lane = threadIdx.x & 31;
    float4 v  = reinterpret_cast<const float4*>(f2 + (size_t)node * 128)[lane];
    float4 bb = reinterpret_cast<const float4*>(b2)[lane];
    float4 wc = reinterpret_cast<const float4*>(Wc)[lane];
    float s = fmaxf(v.x + bb.x, 0.f) * wc.x + fmaxf(v.y + bb.y, 0.f) * wc.y +
              fmaxf(v.z + bb.z, 0.f) * wc.z + fmaxf(v.w + bb.w, 0.f) * wc.w;
#pragma unroll
    for (int o = 16; o; o >>= 1) s += __shfl_down_sync(0xffffffffu, s, o);
    if (lane == 0) {
        int g = batch[node];
        atomicAdd(&psum[g], s);
        atomicAdd(&pcnt[g], 1.f);
    }
}

__global__ void final_kernel(const float* __restrict__ psum,
                             const float* __restrict__ pcnt,
                             const float* __restrict__ bc,
                             float* __restrict__ out) {
    int g = threadIdx.x;
    if (g < NB) out[g] = psum[g] / fmaxf(pcnt[g], 1.f) + bc[0];
}

// ---------------- launch ---------------------------------------------------
extern "C" void kernel_launch(void* const* d_in, const int* in_sizes, int n_in,
                              void* d_out, int out_size) {
    const float* x_fact     = (const float*)d_in[0];
    const float* ea_fc      = (const float*)d_in[2];
    const float* ea_cf      = (const float*)d_in[3];
    const int*   fc_src     = (const int*)d_in[4];
    const int*   fc_dst     = (const int*)d_in[5];
    const int*   cf_src     = (const int*)d_in[6];
    const int*   cf_dst     = (const int*)d_in[7];
    const int*   batch_fact = (const int*)d_in[8];
    const float* Wm         = (const float*)d_in[9];
    const float* bm         = (const float*)d_in[10];
    const float* W1_fc      = (const float*)d_in[11];
    const float* b1_fc      = (const float*)d_in[12];
    const float* W2_cf      = (const float*)d_in[17];
    const float* b2_cf      = (const float*)d_in[18];
    const float* Wc         = (const float*)d_in[19];
    const float* bc         = (const float*)d_in[20];
    float* out = (float*)d_out;

    float *wfc, *wcf, *dfcs, *dfcd, *dcfs, *dcfd, *H1, *c1, *H2, *f2, *psum, *pcnt;
    cudaGetSymbolAddress((void**)&wfc,  g_wfc);
    cudaGetSymbolAddress((void**)&wcf,  g_wcf);
    cudaGetSymbolAddress((void**)&dfcs, g_dfc_s);
    cudaGetSymbolAddress((void**)&dfcd, g_dfc_d);
    cudaGetSymbolAddress((void**)&dcfs, g_dcf_s);
    cudaGetSymbolAddress((void**)&dcfd, g_dcf_d);
    cudaGetSymbolAddress((void**)&H1,   g_H1);
    cudaGetSymbolAddress((void**)&c1,   g_c1);
    cudaGetSymbolAddress((void**)&H2,   g_H2);
    cudaGetSymbolAddress((void**)&f2,   g_f2);
    cudaGetSymbolAddress((void**)&psum, g_psum);
    cudaGetSymbolAddress((void**)&pcnt, g_pcnt);

    cudaMemsetAsync(dfcs, 0, NFACT * sizeof(float));
    cudaMemsetAsync(dfcd, 0, NCOMP * sizeof(float));
    cudaMemsetAsync(dcfs, 0, NCOMP * sizeof(float));
    cudaMemsetAsync(dcfd, 0, NFACT * sizeof(float));
    cudaMemsetAsync(c1,   0, (size_t)NCOMP * HID * sizeof(float));
    cudaMemsetAsync(f2,   0, (size_t)NFACT * HID * sizeof(float));
    cudaMemsetAsync(psum, 0, NB * sizeof(float));
    cudaMemsetAsync(pcnt, 0, NB * sizeof(float));

    // 1,2: edge gates + degrees
    gate_deg_kernel<<<(NEDGE + 255) / 256, 256>>>(ea_fc, fc_src, fc_dst, Wm, bm,
                                                  wfc, dfcs, dfcd, NEDGE);
    gate_deg_kernel<<<(NEDGE + 255) / 256, 256>>>(ea_cf, cf_src, cf_dst, Wm, bm,
                                                  wcf, dcfs, dcfd, NEDGE);
    // 3,4: fc-relation inv-sqrt degrees
    invsqrt_kernel<<<(NFACT + 255) / 256, 256>>>(dfcs, NFACT);
    invsqrt_kernel<<<(NCOMP + 255) / 256, 256>>>(dfcd, NCOMP);
    // 5: GEMM1 (positioned 5th so ncu's capture window lands on it)
    mma_gemm128_kernel<<<(NFACT + 127) / 128, 256>>>(x_fact, W1_fc, nullptr,
                                                     H1, NFACT, DFACT);
    // 6,7: cf-relation inv-sqrt degrees
    invsqrt_kernel<<<(NCOMP + 255) / 256, 256>>>(dcfs, NCOMP);
    invsqrt_kernel<<<(NFACT + 255) / 256, 256>>>(dcfd, NFACT);

    // 8: aggregate layer-1 fact->company (c1 pre-activation)
    agg128_kernel<<<(NEDGE + 7) / 8, 256>>>(c1, H1, fc_src, fc_dst,
                                            wfc, dfcs, dfcd, NEDGE);
    // 9: GEMM2 with fused relu(c1 + b1_fc) on the A operand
    mma_gemm128_kernel<<<(NCOMP + 127) / 128, 256>>>(c1, W2_cf, b1_fc,
                                                     H2, NCOMP, HID);
    // 10: aggregate layer-2 company->fact
    agg128_kernel<<<(NEDGE + 7) / 8, 256>>>(f2, H2, cf_src, cf_dst,
                                            wcf, dcfs, dcfd, NEDGE);

    // 11,12: fused relu+bias+classifier-dot+mean-pool
    pool_kernel<<<(NFACT + 7) / 8, 256>>>(f2, b2_cf, Wc, batch_fact,
                                          psum, pcnt, NFACT);
    final_kernel<<<1, NB>>>(psum, pcnt, bc, out);
}

// round 4
// speedup vs baseline: 1.5503x; 1.0515x over previous
#include <cuda_runtime.h>
#include <cuda_bf16.h>
#include <cstdint>

#define NFACT 100000
#define NCOMP 10000
#define NEDGE 800000
#define DFACT 768
#define HID   128
#define NB    256

#define APITCH 36
#define BPITCH 132
#define ASTG   (128 * APITCH)
#define BSTG   (32 * BPITCH)
#define SMEM_BYTES ((3 * (ASTG + BSTG)) * 4)

// ---------------- scratch (device globals; no allocation allowed) ----------
__device__ float g_wfc[NEDGE];
__device__ float g_wcf[NEDGE];
__device__ float g_dfc_s[NFACT];
__device__ float g_dfc_d[NCOMP];
__device__ float g_dcf_s[NCOMP];
__device__ float g_dcf_d[NFACT];
__device__ float g_H1[(size_t)NFACT * HID];
__device__ float g_c1[(size_t)NCOMP * HID];
__device__ float g_H2[(size_t)NCOMP * HID];
__device__ float g_f2[(size_t)NFACT * HID];
__device__ float g_psum[NB];
__device__ float g_pcnt[NB];

// ---------------- helpers --------------------------------------------------
// round-to-nearest tf32 conversion — REQUIRED for accuracy (truncation's
// -0.5ulp bias accumulates coherently over K and blew past 1e-3 in R3).
__device__ __forceinline__ uint32_t f2tf32(float x) {
    uint32_t r;
    asm("cvt.rna.tf32.f32 %0, %1;" : "=r"(r) : "f"(x));
    return r;
}

__device__ __forceinline__ void mma_tf32(float* c, const uint32_t* a, const uint32_t* b) {
    asm volatile(
        "mma.sync.aligned.m16n8k8.row.col.f32.tf32.tf32.f32 "
        "{%0,%1,%2,%3}, {%4,%5,%6,%7}, {%8,%9}, {%0,%1,%2,%3};"
        : "+f"(c[0]), "+f"(c[1]), "+f"(c[2]), "+f"(c[3])
        : "r"(a[0]), "r"(a[1]), "r"(a[2]), "r"(a[3]), "r"(b[0]), "r"(b[1]));
}

__device__ __forceinline__ void cp_async16(float* sptr, const float* gptr, int nbytes) {
    uint32_t sa = (uint32_t)__cvta_generic_to_shared(sptr);
    asm volatile("cp.async.cg.shared.global [%0], [%1], 16, %2;"
                 :: "r"(sa), "l"(gptr), "r"(nbytes));
}
#define CP_COMMIT() asm volatile("cp.async.commit_group;")
#define CP_WAIT1()  asm volatile("cp.async.wait_group 1;")

// ---------------- kernels --------------------------------------------------

__global__ void gate_deg_kernel(const float* __restrict__ ea,
                                const int* __restrict__ src,
                                const int* __restrict__ dst,
                                const float* __restrict__ Wm,
                                const float* __restrict__ bm,
                                float* __restrict__ w,
                                float* __restrict__ deg_s,
                                float* __restrict__ deg_d,
                                int E) {
    int e = blockIdx.x * blockDim.x + threadIdx.x;
    if (e >= E) return;
    float a0 = ea[2 * e + 0];
    float a1 = ea[2 * e + 1];
    float z  = a0 * Wm[0] + a1 * Wm[1] + bm[0];
    float ww = 1.f / (1.f + expf(-z));
    w[e] = ww;
    atomicAdd(&deg_s[src[e]], ww);
    atomicAdd(&deg_d[dst[e]], ww);
}

__global__ void invsqrt_kernel(float* __restrict__ d, int n) {
    int i = blockIdx.x * blockDim.x + threadIdx.x;
    if (i >= n) return;
    float v = d[i];
    d[i] = (v > 0.f) ? rsqrtf(v) : 0.f;
}

// C[M,128] = act(A[M,K]) @ B[K,128], tf32 MMA, 3-stage cp.async pipeline.
// act(x) = relu(x + abias[k]) when HASBIAS. cvt.rna.tf32 applied to
// register fragments right before the MMA (round-to-nearest, cheap).
// BM=128, BN=128, BK=32, 256 threads, warp tile 32x64.
template <bool HASBIAS>
__global__ __launch_bounds__(256) void mma_gemm128_async(
        const float* __restrict__ A, const float* __restrict__ Bw,
        const float* __restrict__ abias, float* __restrict__ C,
        int M, int K) {
    extern __shared__ float smem[];
    float* Asm = smem;               // 3 stages of [128][APITCH]
    float* Bsm = smem + 3 * ASTG;    // 3 stages of [32][BPITCH]

    const int tid  = threadIdx.x;
    const int wid  = tid >> 5;
    const int lane = tid & 31;
    const int gid  = lane >> 2;
    const int tid4 = lane & 3;
    const int wm   = (wid & 3) * 32;
    const int wn   = (wid >> 2) * 64;
    const int row0 = blockIdx.x * 128;
    const int ntiles = K >> 5;

    float acc[2][8][4];
#pragma unroll
    for (int mi = 0; mi < 2; mi++)
#pragma unroll
        for (int ni = 0; ni < 8; ni++)
#pragma unroll
            for (int j = 0; j < 4; j++) acc[mi][ni][j] = 0.f;

    // cp.async staging indices: 4 float4 each for A and B per thread
    int aR[4], aC[4], bR[4], bC[4];
#pragma unroll
    for (int s = 0; s < 4; s++) {
        int j = tid + s * 256;
        aR[s] = j >> 3;  aC[s] = (j & 7) << 2;
        bR[s] = j >> 5;  bC[s] = (j & 31) << 2;
    }

#define ISSUE_LOAD(t)                                                          \
    do {                                                                       \
        int k0 = (t) << 5;                                                     \
        float* as = Asm + ((t) % 3) * ASTG;                                    \
        float* bs = Bsm + ((t) % 3) * BSTG;                                    \
        _Pragma("unroll")                                                      \
        for (int s = 0; s < 4; s++) {                                          \
            int r = row0 + aR[s];                                              \
            cp_async16(as + aR[s] * APITCH + aC[s],                            \
                       A + (size_t)r * K + k0 + aC[s], (r < M) ? 16 : 0);      \
        }                                                                      \
        _Pragma("unroll")                                                      \
        for (int s = 0; s < 4; s++)                                            \
            cp_async16(bs + bR[s] * BPITCH + bC[s],                            \
                       Bw + (size_t)(k0 + bR[s]) * 128 + bC[s], 16);           \
    } while (0)

    // prologue: stages 0,1 in flight
    ISSUE_LOAD(0); CP_COMMIT();
    if (ntiles > 1) { ISSUE_LOAD(1); }
    CP_COMMIT();

    for (int t = 0; t < ntiles; t++) {
        CP_WAIT1();
        __syncthreads();
        if (t + 2 < ntiles) { ISSUE_LOAD(t + 2); }
        CP_COMMIT();

        const float* as = Asm + (t % 3) * ASTG;
        const float* bs = Bsm + (t % 3) * BSTG;
        const int k0 = t << 5;

#pragma unroll
        for (int kk = 0; kk < 32; kk += 8) {
            uint32_t afr[2][4], bfr[8][2];
            float bias0 = 0.f, bias1 = 0.f;
            if (HASBIAS) {
                bias0 = __ldg(abias + k0 + kk + tid4);
                bias1 = __ldg(abias + k0 + kk + tid4 + 4);
            }
#pragma unroll
            for (int mi = 0; mi < 2; mi++) {
                int r = wm + mi * 16 + gid;
                float a0 = as[r * APITCH + kk + tid4];
                float a1 = as[(r + 8) * APITCH + kk + tid4];
                float a2 = as[r * APITCH + kk + tid4 + 4];
                float a3 = as[(r + 8) * APITCH + kk + tid4 + 4];
                if (HASBIAS) {
                    a0 = fmaxf(a0 + bias0, 0.f);
                    a1 = fmaxf(a1 + bias0, 0.f);
                    a2 = fmaxf(a2 + bias1, 0.f);
                    a3 = fmaxf(a3 + bias1, 0.f);
                }
                afr[mi][0] = f2tf32(a0);
                afr[mi][1] = f2tf32(a1);
                afr[mi][2] = f2tf32(a2);
                afr[mi][3] = f2tf32(a3);
            }
#pragma unroll
            for (int ni = 0; ni < 8; ni++) {
                int c = wn + ni * 8 + gid;
                bfr[ni][0] = f2tf32(bs[(kk + tid4) * BPITCH + c]);
                bfr[ni][1] = f2tf32(bs[(kk + tid4 + 4) * BPITCH + c]);
            }
#pragma unroll
            for (int mi = 0; mi < 2; mi++)
#pragma unroll
                for (int ni = 0; ni < 8; ni++)
                    mma_tf32(acc[mi][ni], afr[mi], bfr[ni]);
        }
        __syncthreads();
    }

#pragma unroll
    for (int mi = 0; mi < 2; mi++)
#pragma unroll
        for (int ni = 0; ni < 8; ni++) {
            int r1 = row0 + wm + mi * 16 + gid;
            int r2 = r1 + 8;
            int c  = wn + ni * 8 + tid4 * 2;
            if (r1 < M)
                *reinterpret_cast<float2*>(C + (size_t)r1 * 128 + c) =
                    make_float2(acc[mi][ni][0], acc[mi][ni][1]);
            if (r2 < M)
                *reinterpret_cast<float2*>(C + (size_t)r2 * 128 + c) =
                    make_float2(acc[mi][ni][2], acc[mi][ni][3]);
        }
#undef ISSUE_LOAD
}

// one warp per edge: out[dst] += norm_e * h[src]  (128 floats, v4 reduction)
__global__ void agg128_kernel(float* __restrict__ out,
                              const float* __restrict__ h,
                              const int* __restrict__ src,
                              const int* __restrict__ dst,
                              const float* __restrict__ w,
                              const float* __restrict__ dis_s,
                              const float* __restrict__ dis_d,
                              int E) {
    int e = blockIdx.x * (blockDim.x >> 5) + (threadIdx.x >> 5);
    if (e >= E) return;
    int lane = threadIdx.x & 31;
    int s = src[e], d = dst[e];
    float nrm = w[e] * dis_s[s] * dis_d[d];
    float4 v = reinterpret_cast<const float4*>(h + (size_t)s * 128)[lane];
    float* op = out + (size_t)d * 128 + lane * 4;
    asm volatile("red.global.add.v4.f32 [%0], {%1,%2,%3,%4};"
                 :: "l"(op), "f"(nrm * v.x), "f"(nrm * v.y),
                    "f"(nrm * v.z), "f"(nrm * v.w)
                 : "memory");
}

// fused: relu(f2+b2) . Wc per fact node, atomically pooled per graph
__global__ void pool_kernel(const float* __restrict__ f2,
                            const float* __restrict__ b2,
                            const float* __restrict__ Wc,
                            const int* __restrict__ batch,
                            float* __restrict__ psum,
                            float* __restrict__ pcnt, int n) {
    int node = blockIdx.x * (blockDim.x >> 5) + (threadIdx.x >> 5);
    if (node >= n) return;
    int lane = threadIdx.x & 31;
    float4 v  = reinterpret_cast<const float4*>(f2 + (size_t)node * 128)[lane];
    float4 bb = reinterpret_cast<const float4*>(b2)[lane];
    float4 wc = reinterpret_cast<const float4*>(Wc)[lane];
    float s = fmaxf(v.x + bb.x, 0.f) * wc.x + fmaxf(v.y + bb.y, 0.f) * wc.y +
              fmaxf(v.z + bb.z, 0.f) * wc.z + fmaxf(v.w + bb.w, 0.f) * wc.w;
#pragma unroll
    for (int o = 16; o; o >>= 1) s += __shfl_down_sync(0xffffffffu, s, o);
    if (lane == 0) {
        int g = batch[node];
        atomicAdd(&psum[g], s);
        atomicAdd(&pcnt[g], 1.f);
    }
}

__global__ void final_kernel(const float* __restrict__ psum,
                             const float* __restrict__ pcnt,
                             const float* __restrict__ bc,
                             float* __restrict__ out) {
    int g = threadIdx.x;
    if (g < NB) out[g] = psum[g] / fmaxf(pcnt[g], 1.f) + bc[0];
}

// ---------------- launch ---------------------------------------------------
extern "C" void kernel_launch(void* const* d_in, const int* in_sizes, int n_in,
                              void* d_out, int out_size) {
    const float* x_fact     = (const float*)d_in[0];
    const float* ea_fc      = (const float*)d_in[2];
    const float* ea_cf      = (const float*)d_in[3];
    const int*   fc_src     = (const int*)d_in[4];
    const int*   fc_dst     = (const int*)d_in[5];
    const int*   cf_src     = (const int*)d_in[6];
    const int*   cf_dst     = (const int*)d_in[7];
    const int*   batch_fact = (const int*)d_in[8];
    const float* Wm         = (const float*)d_in[9];
    const float* bm         = (const float*)d_in[10];
    const float* W1_fc      = (const float*)d_in[11];
    const float* b1_fc      = (const float*)d_in[12];
    const float* W2_cf      = (const float*)d_in[17];
    const float* b2_cf      = (const float*)d_in[18];
    const float* Wc         = (const float*)d_in[19];
    const float* bc         = (const float*)d_in[20];
    float* out = (float*)d_out;

    float *wfc, *wcf, *dfcs, *dfcd, *dcfs, *dcfd, *H1, *c1, *H2, *f2, *psum, *pcnt;
    cudaGetSymbolAddress((void**)&wfc,  g_wfc);
    cudaGetSymbolAddress((void**)&wcf,  g_wcf);
    cudaGetSymbolAddress((void**)&dfcs, g_dfc_s);
    cudaGetSymbolAddress((void**)&dfcd, g_dfc_d);
    cudaGetSymbolAddress((void**)&dcfs, g_dcf_s);
    cudaGetSymbolAddress((void**)&dcfd, g_dcf_d);
    cudaGetSymbolAddress((void**)&H1,   g_H1);
    cudaGetSymbolAddress((void**)&c1,   g_c1);
    cudaGetSymbolAddress((void**)&H2,   g_H2);
    cudaGetSymbolAddress((void**)&f2,   g_f2);
    cudaGetSymbolAddress((void**)&psum, g_psum);
    cudaGetSymbolAddress((void**)&pcnt, g_pcnt);

    cudaFuncSetAttribute(mma_gemm128_async<false>,
                         cudaFuncAttributeMaxDynamicSharedMemorySize, SMEM_BYTES);
    cudaFuncSetAttribute(mma_gemm128_async<true>,
                         cudaFuncAttributeMaxDynamicSharedMemorySize, SMEM_BYTES);

    cudaMemsetAsync(dfcs, 0, NFACT * sizeof(float));
    cudaMemsetAsync(dfcd, 0, NCOMP * sizeof(float));
    cudaMemsetAsync(dcfs, 0, NCOMP * sizeof(float));
    cudaMemsetAsync(dcfd, 0, NFACT * sizeof(float));
    cudaMemsetAsync(c1,   0, (size_t)NCOMP * HID * sizeof(float));
    cudaMemsetAsync(f2,   0, (size_t)NFACT * HID * sizeof(float));
    cudaMemsetAsync(psum, 0, NB * sizeof(float));
    cudaMemsetAsync(pcnt, 0, NB * sizeof(float));

    // launches 1-5
    gate_deg_kernel<<<(NEDGE + 255) / 256, 256>>>(ea_fc, fc_src, fc_dst, Wm, bm,
                                                  wfc, dfcs, dfcd, NEDGE);
    gate_deg_kernel<<<(NEDGE + 255) / 256, 256>>>(ea_cf, cf_src, cf_dst, Wm, bm,
                                                  wcf, dcfs, dcfd, NEDGE);
    invsqrt_kernel<<<(NFACT + 255) / 256, 256>>>(dfcs, NFACT);
    invsqrt_kernel<<<(NCOMP + 255) / 256, 256>>>(dfcd, NCOMP);
    invsqrt_kernel<<<(NCOMP + 255) / 256, 256>>>(dcfs, NCOMP);
    // launch 6: GEMM1 (ncu -s 5 -c 1 profiles this one)
    mma_gemm128_async<false><<<(NFACT + 127) / 128, 256, SMEM_BYTES>>>(
        x_fact, W1_fc, nullptr, H1, NFACT, DFACT);
    // launch 7
    invsqrt_kernel<<<(NFACT + 255) / 256, 256>>>(dcfd, NFACT);

    // 8: aggregate layer-1 fact->company (c1 pre-activation)
    agg128_kernel<<<(NEDGE + 7) / 8, 256>>>(c1, H1, fc_src, fc_dst,
                                            wfc, dfcs, dfcd, NEDGE);
    // 9: GEMM2 with fused relu(c1 + b1_fc) on the A operand
    mma_gemm128_async<true><<<(NCOMP + 127) / 128, 256, SMEM_BYTES>>>(
        c1, W2_cf, b1_fc, H2, NCOMP, HID);
    // 10: aggregate layer-2 company->fact
    agg128_kernel<<<(NEDGE + 7) / 8, 256>>>(f2, H2, cf_src, cf_dst,
                                            wcf, dcfs, dcfd, NEDGE);

    // 11,12: fused relu+bias+classifier-dot+mean-pool
    pool_kernel<<<(NFACT + 7) / 8, 256>>>(f2, b2_cf, Wc, batch_fact,
                                          psum, pcnt, NFACT);
    final_kernel<<<1, NB>>>(psum, pcnt, bc, out);
}

// round 6
// speedup vs baseline: 1.8238x; 1.1764x over previous
#include <cuda_runtime.h>
#include <cuda_bf16.h>
#include <cstdint>

#define NFACT 100000
#define NCOMP 10000
#define NEDGE 800000
#define DFACT 768
#define HID   128
#define NB    256

#define APITCH 36
#define BPITCH 132
#define ASTG   (128 * APITCH)
#define BSTG   (32 * BPITCH)
#define SMEM_BYTES ((3 * (ASTG + BSTG)) * 4)

#define SCAN_BS 256

// ---------------- scratch (device globals; no allocation allowed) ----------
__device__ float g_wfc[NEDGE];
__device__ float g_wcf[NEDGE];
__device__ float g_dfc_s[NFACT];
__device__ float g_dfc_d[NCOMP];
__device__ float g_dcf_s[NCOMP];
__device__ float g_dcf_d[NFACT];
__device__ float g_W1r[(size_t)DFACT * HID];   // tf32-pre-rounded weights
__device__ float g_W2r[(size_t)HID * HID];
__device__ float g_H1[(size_t)NFACT * HID];
__device__ float g_c1[(size_t)NCOMP * HID];
__device__ float g_H2[(size_t)NCOMP * HID];
__device__ float g_f2[(size_t)NFACT * HID];
__device__ float g_psum[NB];
__device__ float g_pcnt[NB];
// CSR build scratch
__device__ int   g_cntc[NCOMP];
__device__ int   g_cntf[NFACT];
__device__ int   g_bsum[1024];
__device__ int   g_rpc[NCOMP + 1];
__device__ int   g_rpf[NFACT + 1];
__device__ int   g_curc[NCOMP];
__device__ int   g_curf[NFACT];
__device__ uint2 g_pfc[NEDGE];   // {src, w*dis_s[src]} sorted by dst (company)
__device__ uint2 g_pcf[NEDGE];   // {src, w*dis_s[src]} sorted by dst (fact)

// ---------------- helpers --------------------------------------------------
__device__ __forceinline__ uint32_t f2tf32(float x) {
    uint32_t r;
    asm("cvt.rna.tf32.f32 %0, %1;" : "=r"(r) : "f"(x));
    return r;
}

__device__ __forceinline__ void mma_tf32(float* c, const uint32_t* a, const uint32_t* b) {
    asm volatile(
        "mma.sync.aligned.m16n8k8.row.col.f32.tf32.tf32.f32 "
        "{%0,%1,%2,%3}, {%4,%5,%6,%7}, {%8,%9}, {%0,%1,%2,%3};"
        : "+f"(c[0]), "+f"(c[1]), "+f"(c[2]), "+f"(c[3])
        : "r"(a[0]), "r"(a[1]), "r"(a[2]), "r"(a[3]), "r"(b[0]), "r"(b[1]));
}

__device__ __forceinline__ void cp_async16(float* sptr, const float* gptr, int nbytes) {
    uint32_t sa = (uint32_t)__cvta_generic_to_shared(sptr);
    asm volatile("cp.async.cg.shared.global [%0], [%1], 16, %2;"
                 :: "r"(sa), "l"(gptr), "r"(nbytes));
}
#define CP_COMMIT() asm volatile("cp.async.commit_group;")
#define CP_WAIT1()  asm volatile("cp.async.wait_group 1;")

// ---------------- small kernels --------------------------------------------

__global__ void gate_deg_kernel(const float* __restrict__ ea,
                                const int* __restrict__ src,
                                const int* __restrict__ dst,
                                const float* __restrict__ Wm,
                                const float* __restrict__ bm,
                                float* __restrict__ w,
                                float* __restrict__ deg_s,
                                float* __restrict__ deg_d,
                                int E) {
    int e = blockIdx.x * blockDim.x + threadIdx.x;
    if (e >= E) return;
    float a0 = ea[2 * e + 0];
    float a1 = ea[2 * e + 1];
    float z  = a0 * Wm[0] + a1 * Wm[1] + bm[0];
    float ww = 1.f / (1.f + expf(-z));
    w[e] = ww;
    atomicAdd(&deg_s[src[e]], ww);
    atomicAdd(&deg_d[dst[e]], ww);
}

__global__ void invsqrt_kernel(float* __restrict__ d, int n) {
    int i = blockIdx.x * blockDim.x + threadIdx.x;
    if (i >= n) return;
    float v = d[i];
    d[i] = (v > 0.f) ? rsqrtf(v) : 0.f;
}

// tf32-pre-round W1 (768x128) and W2 (128x128) in their native [k][n] layouts
__global__ void prep_w_kernel(const float* __restrict__ W1, const float* __restrict__ W2,
                              float* __restrict__ W1r, float* __restrict__ W2r) {
    int i = blockIdx.x * blockDim.x + threadIdx.x;
    int n1 = DFACT * HID;
    if (i < n1) {
        W1r[i] = __uint_as_float(f2tf32(W1[i]));
    } else if (i < n1 + HID * HID) {
        int j = i - n1;
        W2r[j] = __uint_as_float(f2tf32(W2[j]));
    }
}

// ---------------- CSR build ------------------------------------------------
__global__ void hist_kernel(const int* __restrict__ dst, int* __restrict__ cnt, int E) {
    int e = blockIdx.x * blockDim.x + threadIdx.x;
    if (e < E) atomicAdd(&cnt[dst[e]], 1);
}

__global__ void scan_bsum_kernel(const int* __restrict__ cnt, int n, int* __restrict__ bsum) {
    __shared__ int sh[SCAN_BS];
    int i = blockIdx.x * SCAN_BS + threadIdx.x;
    sh[threadIdx.x] = (i < n) ? cnt[i] : 0;
    __syncthreads();
    for (int o = SCAN_BS / 2; o; o >>= 1) {
        if (threadIdx.x < o) sh[threadIdx.x] += sh[threadIdx.x + o];
        __syncthreads();
    }
    if (threadIdx.x == 0) bsum[blockIdx.x] = sh[0];
}

// single block, 1024 threads: exclusive scan of bsum (nb <= 1024), rowptr[n] = total
__global__ void scan_tops_kernel(int* __restrict__ bsum, int nb,
                                 int* __restrict__ rowptr, int n) {
    __shared__ int sh[1024];
    int tid = threadIdx.x;
    int v = (tid < nb) ? bsum[tid] : 0;
    sh[tid] = v;
    __syncthreads();
    for (int o = 1; o < 1024; o <<= 1) {
        int t = (tid >= o) ? sh[tid - o] : 0;
        __syncthreads();
        sh[tid] += t;
        __syncthreads();
    }
    if (tid < nb) bsum[tid] = sh[tid] - v;   // exclusive
    if (tid == 0) rowptr[n] = sh[1023];      // grand total
}

__global__ void scan_write_kernel(const int* __restrict__ cnt, const int* __restrict__ bsum,
                                  int n, int* __restrict__ rowptr, int* __restrict__ cur) {
    __shared__ int sh[SCAN_BS];
    int tid = threadIdx.x;
    int i = blockIdx.x * SCAN_BS + tid;
    int v = (i < n) ? cnt[i] : 0;
    sh[tid] = v;
    __syncthreads();
    for (int o = 1; o < SCAN_BS; o <<= 1) {
        int t = (tid >= o) ? sh[tid - o] : 0;
        __syncthreads();
        sh[tid] += t;
        __syncthreads();
    }
    if (i < n) {
        int ex = sh[tid] - v + bsum[blockIdx.x];
        rowptr[i] = ex;
        cur[i] = ex;
    }
}

// scatter packed {src, w*dis_s[src]} into dst-sorted slots
__global__ void scatter_kernel(const int* __restrict__ src, const int* __restrict__ dst,
                               const float* __restrict__ w, const float* __restrict__ dis_s,
                               int* __restrict__ cur, uint2* __restrict__ packed, int E) {
    int e = blockIdx.x * blockDim.x + threadIdx.x;
    if (e >= E) return;
    int d = dst[e];
    int pos = atomicAdd(&cur[d], 1);
    int s = src[e];
    packed[pos] = make_uint2((uint32_t)s, __float_as_uint(w[e] * dis_s[s]));
}

// gather: one warp per dst node; out[node] = dis_d[node] * sum_e w'*h[src]
__global__ void gather_kernel(float* __restrict__ out, const float* __restrict__ h,
                              const uint2* __restrict__ packed,
                              const int* __restrict__ rowptr,
                              const float* __restrict__ dis_d, int n) {
    int node = blockIdx.x * (blockDim.x >> 5) + (threadIdx.x >> 5);
    if (node >= n) return;
    int lane = threadIdx.x & 31;
    int r0 = __ldg(rowptr + node), r1 = __ldg(rowptr + node + 1);
    float4 acc = make_float4(0.f, 0.f, 0.f, 0.f);
    for (int base = r0; base < r1; base += 32) {
        int nit = min(32, r1 - base);
        uint2 meta = (lane < nit) ? __ldg(packed + base + lane) : make_uint2(0u, 0u);
        for (int j = 0; j < nit; j++) {
            int   s  = __shfl_sync(0xffffffffu, (int)meta.x, j);
            float wv = __uint_as_float(__shfl_sync(0xffffffffu, meta.y, j));
            float4 v = reinterpret_cast<const float4*>(h + (size_t)s * 128)[lane];
            acc.x += wv * v.x; acc.y += wv * v.y;
            acc.z += wv * v.z; acc.w += wv * v.w;
        }
    }
    float dd = __ldg(dis_d + node);
    acc.x *= dd; acc.y *= dd; acc.z *= dd; acc.w *= dd;
    reinterpret_cast<float4*>(out + (size_t)node * 128)[lane] = acc;
}

// ---------------- GEMM: mma.sync tf32, cp.async 3-stage --------------------
// B (weights) pre-rounded to tf32 bits -> no cvt on B path. A keeps cvt.rna.
template <bool HASBIAS>
__global__ __launch_bounds__(256) void mma_gemm128_async(
        const float* __restrict__ A, const float* __restrict__ Bw,
        const float* __restrict__ abias, float* __restrict__ C,
        int M, int K) {
    extern __shared__ float smem[];
    float* Asm = smem;
    float* Bsm = smem + 3 * ASTG;

    const int tid  = threadIdx.x;
    const int wid  = tid >> 5;
    const int lane = tid & 31;
    const int gid  = lane >> 2;
    const int tid4 = lane & 3;
    const int wm   = (wid & 3) * 32;
    const int wn   = (wid >> 2) * 64;
    const int row0 = blockIdx.x * 128;
    const int ntiles = K >> 5;

    float acc[2][8][4];
#pragma unroll
    for (int mi = 0; mi < 2; mi++)
#pragma unroll
        for (int ni = 0; ni < 8; ni++)
#pragma unroll
            for (int j = 0; j < 4; j++) acc[mi][ni][j] = 0.f;

    int aR[4], aC[4], bR[4], bC[4];
#pragma unroll
    for (int s = 0; s < 4; s++) {
        int j = tid + s * 256;
        aR[s] = j >> 3;  aC[s] = (j & 7) << 2;
        bR[s] = j >> 5;  bC[s] = (j & 31) << 2;
    }

#define ISSUE_LOAD(t)                                                          \
    do {                                                                       \
        int k0 = (t) << 5;                                                     \
        float* as = Asm + ((t) % 3) * ASTG;                                    \
        float* bs = Bsm + ((t) % 3) * BSTG;                                    \
        _Pragma("unroll")                                                      \
        for (int s = 0; s < 4; s++) {                                          \
            int r = row0 + aR[s];                                              \
            cp_async16(as + aR[s] * APITCH + aC[s],                            \
                       A + (size_t)r * K + k0 + aC[s], (r < M) ? 16 : 0);      \
        }                                                                      \
        _Pragma("unroll")                                                      \
        for (int s = 0; s < 4; s++)                                            \
            cp_async16(bs + bR[s] * BPITCH + bC[s],                            \
                       Bw + (size_t)(k0 + bR[s]) * 128 + bC[s], 16);           \
    } while (0)

    ISSUE_LOAD(0); CP_COMMIT();
    if (ntiles > 1) { ISSUE_LOAD(1); }
    CP_COMMIT();

    for (int t = 0; t < ntiles; t++) {
        CP_WAIT1();
        __syncthreads();
        if (t + 2 < ntiles) { ISSUE_LOAD(t + 2); }
        CP_COMMIT();

        const float* as = Asm + (t % 3) * ASTG;
        const float* bs = Bsm + (t % 3) * BSTG;
        const int k0 = t << 5;

#pragma unroll
        for (int kk = 0; kk < 32; kk += 8) {
            uint32_t afr[2][4], bfr[8][2];
            float bias0 = 0.f, bias1 = 0.f;
            if (HASBIAS) {
                bias0 = __ldg(abias + k0 + kk + tid4);
                bias1 = __ldg(abias + k0 + kk + tid4 + 4);
            }
#pragma unroll
            for (int mi = 0; mi < 2; mi++) {
                int r = wm + mi * 16 + gid;
                float a0 = as[r * APITCH + kk + tid4];
                float a1 = as[(r + 8) * APITCH + kk + tid4];
                float a2 = as[r * APITCH + kk + tid4 + 4];
                float a3 = as[(r + 8) * APITCH + kk + tid4 + 4];
                if (HASBIAS) {
                    a0 = fmaxf(a0 + bias0, 0.f);
                    a1 = fmaxf(a1 + bias0, 0.f);
                    a2 = fmaxf(a2 + bias1, 0.f);
                    a3 = fmaxf(a3 + bias1, 0.f);
                }
                afr[mi][0] = f2tf32(a0);
                afr[mi][1] = f2tf32(a1);
                afr[mi][2] = f2tf32(a2);
                afr[mi][3] = f2tf32(a3);
            }
#pragma unroll
            for (int ni = 0; ni < 8; ni++) {
                int c = wn + ni * 8 + gid;
                bfr[ni][0] = __float_as_uint(bs[(kk + tid4) * BPITCH + c]);
                bfr[ni][1] = __float_as_uint(bs[(kk + tid4 + 4) * BPITCH + c]);
            }
#pragma unroll
            for (int mi = 0; mi < 2; mi++)
#pragma unroll
                for (int ni = 0; ni < 8; ni++)
                    mma_tf32(acc[mi][ni], afr[mi], bfr[ni]);
        }
        __syncthreads();
    }

#pragma unroll
    for (int mi = 0; mi < 2; mi++)
#pragma unroll
        for (int ni = 0; ni < 8; ni++) {
            int r1 = row0 + wm + mi * 16 + gid;
            int r2 = r1 + 8;
            int c  = wn + ni * 8 + tid4 * 2;
            if (r1 < M)
                *reinterpret_cast<float2*>(C + (size_t)r1 * 128 + c) =
                    make_float2(acc[mi][ni][0], acc[mi][ni][1]);
            if (r2 < M)
                *reinterpret_cast<float2*>(C + (size_t)r2 * 128 + c) =
                    make_float2(acc[mi][ni][2], acc[mi][ni][3]);
        }
#undef ISSUE_LOAD
}

// fused: relu(f2+b2) . Wc per fact node, atomically pooled per graph
__global__ void pool_kernel(const float* __restrict__ f2,
                            const float* __restrict__ b2,
                            const float* __restrict__ Wc,
                            const int* __restrict__ batch,
                            float* __restrict__ psum,
                            float* __restrict__ pcnt, int n) {
    int node = blockIdx.x * (blockDim.x >> 5) + (threadIdx.x >> 5);
    if (node >= n) return;
    int lane = threadIdx.x & 31;
    float4 v  = reinterpret_cast<const float4*>(f2 + (size_t)node * 128)[lane];
    float4 bb = reinterpret_cast<const float4*>(b2)[lane];
    float4 wc = reinterpret_cast<const float4*>(Wc)[lane];
    float s = fmaxf(v.x + bb.x, 0.f) * wc.x + fmaxf(v.y + bb.y, 0.f) * wc.y +
              fmaxf(v.z + bb.z, 0.f) * wc.z + fmaxf(v.w + bb.w, 0.f) * wc.w;
#pragma unroll
    for (int o = 16; o; o >>= 1) s += __shfl_down_sync(0xffffffffu, s, o);
    if (lane == 0) {
        int g = batch[node];
        atomicAdd(&psum[g], s);
        atomicAdd(&pcnt[g], 1.f);
    }
}

__global__ void final_kernel(const float* __restrict__ psum,
                             const float* __restrict__ pcnt,
                             const float* __restrict__ bc,
                             float* __restrict__ out) {
    int g = threadIdx.x;
    if (g < NB) out[g] = psum[g] / fmaxf(pcnt[g], 1.f) + bc[0];
}

// ---------------- launch ---------------------------------------------------
extern "C" void kernel_launch(void* const* d_in, const int* in_sizes, int n_in,
                              void* d_out, int out_size) {
    const float* x_fact     = (const float*)d_in[0];
    const float* ea_fc      = (const float*)d_in[2];
    const float* ea_cf      = (const float*)d_in[3];
    const int*   fc_src     = (const int*)d_in[4];
    const int*   fc_dst     = (const int*)d_in[5];
    const int*   cf_src     = (const int*)d_in[6];
    const int*   cf_dst     = (const int*)d_in[7];
    const int*   batch_fact = (const int*)d_in[8];
    const float* Wm         = (const float*)d_in[9];
    const float* bm         = (const float*)d_in[10];
    const float* W1_fc      = (const float*)d_in[11];
    const float* b1_fc      = (const float*)d_in[12];
    const float* W2_cf      = (const float*)d_in[17];
    const float* b2_cf      = (const float*)d_in[18];
    const float* Wc         = (const float*)d_in[19];
    const float* bc         = (const float*)d_in[20];
    float* out = (float*)d_out;

    float *wfc, *wcf, *dfcs, *dfcd, *dcfs, *dcfd, *W1r, *W2r, *H1, *c1, *H2, *f2, *psum, *pcnt;
    int *cntc, *cntf, *bsum, *rpc, *rpf, *curc, *curf;
    uint2 *pfc, *pcf;
    cudaGetSymbolAddress((void**)&wfc,  g_wfc);
    cudaGetSymbolAddress((void**)&wcf,  g_wcf);
    cudaGetSymbolAddress((void**)&dfcs, g_dfc_s);
    cudaGetSymbolAddress((void**)&dfcd, g_dfc_d);
    cudaGetSymbolAddress((void**)&dcfs, g_dcf_s);
    cudaGetSymbolAddress((void**)&dcfd, g_dcf_d);
    cudaGetSymbolAddress((void**)&W1r,  g_W1r);
    cudaGetSymbolAddress((void**)&W2r,  g_W2r);
    cudaGetSymbolAddress((void**)&H1,   g_H1);
    cudaGetSymbolAddress((void**)&c1,   g_c1);
    cudaGetSymbolAddress((void**)&H2,   g_H2);
    cudaGetSymbolAddress((void**)&f2,   g_f2);
    cudaGetSymbolAddress((void**)&psum, g_psum);
    cudaGetSymbolAddress((void**)&pcnt, g_pcnt);
    cudaGetSymbolAddress((void**)&cntc, g_cntc);
    cudaGetSymbolAddress((void**)&cntf, g_cntf);
    cudaGetSymbolAddress((void**)&bsum, g_bsum);
    cudaGetSymbolAddress((void**)&rpc,  g_rpc);
    cudaGetSymbolAddress((void**)&rpf,  g_rpf);
    cudaGetSymbolAddress((void**)&curc, g_curc);
    cudaGetSymbolAddress((void**)&curf, g_curf);
    cudaGetSymbolAddress((void**)&pfc,  g_pfc);
    cudaGetSymbolAddress((void**)&pcf,  g_pcf);

    cudaFuncSetAttribute(mma_gemm128_async<false>,
                         cudaFuncAttributeMaxDynamicSharedMemorySize, SMEM_BYTES);
    cudaFuncSetAttribute(mma_gemm128_async<true>,
                         cudaFuncAttributeMaxDynamicSharedMemorySize, SMEM_BYTES);

    cudaMemsetAsync(dfcs, 0, NFACT * sizeof(float));
    cudaMemsetAsync(dfcd, 0, NCOMP * sizeof(float));
    cudaMemsetAsync(dcfs, 0, NCOMP * sizeof(float));
    cudaMemsetAsync(dcfd, 0, NFACT * sizeof(float));
    cudaMemsetAsync(cntc, 0, NCOMP * sizeof(int));
    cudaMemsetAsync(cntf, 0, NFACT * sizeof(int));
    cudaMemsetAsync(psum, 0, NB * sizeof(float));
    cudaMemsetAsync(pcnt, 0, NB * sizeof(float));

    const int nbC = (NCOMP + SCAN_BS - 1) / SCAN_BS;   // 40
    const int nbF = (NFACT + SCAN_BS - 1) / SCAN_BS;   // 391

    // 1,2: edge gates + degrees
    gate_deg_kernel<<<(NEDGE + 255) / 256, 256>>>(ea_fc, fc_src, fc_dst, Wm, bm,
                                                  wfc, dfcs, dfcd, NEDGE);
    gate_deg_kernel<<<(NEDGE + 255) / 256, 256>>>(ea_cf, cf_src, cf_dst, Wm, bm,
                                                  wcf, dcfs, dcfd, NEDGE);
    // 3: pre-round weights
    prep_w_kernel<<<(DFACT * HID + HID * HID + 255) / 256, 256>>>(W1_fc, W2_cf, W1r, W2r);
    // 4: dfcs inv-sqrt (needed by scatter_fc)
    invsqrt_kernel<<<(NFACT + 255) / 256, 256>>>(dfcs, NFACT);
    // 5: GEMM1 — ncu capture window target
    mma_gemm128_async<false><<<(NFACT + 127) / 128, 256, SMEM_BYTES>>>(
        x_fact, W1r, nullptr, H1, NFACT, DFACT);
    // 6-8: remaining inv-sqrts
    invsqrt_kernel<<<(NCOMP + 255) / 256, 256>>>(dfcd, NCOMP);
    invsqrt_kernel<<<(NCOMP + 255) / 256, 256>>>(dcfs, NCOMP);
    invsqrt_kernel<<<(NFACT + 255) / 256, 256>>>(dcfd, NFACT);

    // 9-13: CSR build for fc relation (dst = companies)
    hist_kernel<<<(NEDGE + 255) / 256, 256>>>(fc_dst, cntc, NEDGE);
    scan_bsum_kernel<<<nbC, SCAN_BS>>>(cntc, NCOMP, bsum);
    scan_tops_kernel<<<1, 1024>>>(bsum, nbC, rpc, NCOMP);
    scan_write_kernel<<<nbC, SCAN_BS>>>(cntc, bsum, NCOMP, rpc, curc);
    scatter_kernel<<<(NEDGE + 255) / 256, 256>>>(fc_src, fc_dst, wfc, dfcs,
                                                 curc, pfc, NEDGE);
    // 14-18: CSR build for cf relation (dst = facts)
    hist_kernel<<<(NEDGE + 255) / 256, 256>>>(cf_dst, cntf, NEDGE);
    scan_bsum_kernel<<<nbF, SCAN_BS>>>(cntf, NFACT, bsum);
    scan_tops_kernel<<<1, 1024>>>(bsum, nbF, rpf, NFACT);
    scan_write_kernel<<<nbF, SCAN_BS>>>(cntf, bsum, NFACT, rpf, curf);
    scatter_kernel<<<(NEDGE + 255) / 256, 256>>>(cf_src, cf_dst, wcf, dcfs,
                                                 curf, pcf, NEDGE);

    // 19: gather layer-1 -> c1 (pre-activation)
    gather_kernel<<<(NCOMP + 7) / 8, 256>>>(c1, H1, pfc, rpc, dfcd, NCOMP);
    // 20: GEMM2 with fused relu(c1 + b1_fc)
    mma_gemm128_async<true><<<(NCOMP + 127) / 128, 256, SMEM_BYTES>>>(
        c1, W2r, b1_fc, H2, NCOMP, HID);
    // 21: gather layer-2 -> f2
    gather_kernel<<<(NFACT + 7) / 8, 256>>>(f2, H2, pcf, rpf, dcfd, NFACT);

    // 22,23: fused relu+bias+classifier-dot+mean-pool
    pool_kernel<<<(NFACT + 7) / 8, 256>>>(f2, b2_cf, Wc, batch_fact,
                                          psum, pcnt, NFACT);
    final_kernel<<<1, NB>>>(psum, pcnt, bc, out);
}

// round 7
// speedup vs baseline: 2.2408x; 1.2287x over previous
#include <cuda_runtime.h>
#include <cuda_fp16.h>
#include <cstdint>

#define NFACT 100000
#define NCOMP 10000
#define NEDGE 800000
#define DFACT 768
#define HID   128
#define NB    256

#define PITCH 40                 // halves per smem row (bank-conflict-free)
#define STGH  (128 * PITCH)      // halves per stage buffer
#define SCAN_BS 256

// ---------------- scratch (device globals; no allocation allowed) ----------
__device__ float g_wfc[NEDGE];
__device__ float g_wcf[NEDGE];
__device__ float g_dfc_s[NFACT];
__device__ float g_dfc_d[NCOMP];
__device__ float g_dcf_s[NCOMP];
__device__ float g_dcf_d[NFACT];
__device__ __align__(16) __half g_W1t[(size_t)HID * DFACT];  // [n][k] fp16
__device__ __align__(16) __half g_W2t[(size_t)HID * HID];    // [n][k] fp16
__device__ __align__(16) __half g_H1[(size_t)NFACT * HID];
__device__ float g_c1[(size_t)NCOMP * HID];
__device__ __align__(16) __half g_H2[(size_t)NCOMP * HID];
__device__ __align__(16) __half g_f2[(size_t)NFACT * HID];
__device__ float g_psum[NB];
__device__ float g_pcnt[NB];
// CSR build scratch
__device__ int   g_cntc[NCOMP];
__device__ int   g_cntf[NFACT];
__device__ int   g_bsum[1024];
__device__ int   g_rpc[NCOMP + 1];
__device__ int   g_rpf[NFACT + 1];
__device__ int   g_curc[NCOMP];
__device__ int   g_curf[NFACT];
__device__ uint2 g_pfc[NEDGE];
__device__ uint2 g_pcf[NEDGE];

// ---------------- helpers --------------------------------------------------
__device__ __forceinline__ void mma_f16(float* c, const uint32_t* a, const uint32_t* b) {
    asm volatile(
        "mma.sync.aligned.m16n8k16.row.col.f32.f16.f16.f32 "
        "{%0,%1,%2,%3}, {%4,%5,%6,%7}, {%8,%9}, {%0,%1,%2,%3};"
        : "+f"(c[0]), "+f"(c[1]), "+f"(c[2]), "+f"(c[3])
        : "r"(a[0]), "r"(a[1]), "r"(a[2]), "r"(a[3]), "r"(b[0]), "r"(b[1]));
}
#define CP_COMMIT() asm volatile("cp.async.commit_group;")
#define CP_WAIT1()  asm volatile("cp.async.wait_group 1;")

// ---------------- small kernels --------------------------------------------
// edge gate + degree accumulation + CSR histogram (fused)
__global__ void gate_deg_kernel(const float* __restrict__ ea,
                                const int* __restrict__ src,
                                const int* __restrict__ dst,
                                const float* __restrict__ Wm,
                                const float* __restrict__ bm,
                                float* __restrict__ w,
                                float* __restrict__ deg_s,
                                float* __restrict__ deg_d,
                                int* __restrict__ cnt,
                                int E) {
    int e = blockIdx.x * blockDim.x + threadIdx.x;
    if (e >= E) return;
    float a0 = ea[2 * e + 0];
    float a1 = ea[2 * e + 1];
    float z  = a0 * Wm[0] + a1 * Wm[1] + bm[0];
    float ww = 1.f / (1.f + expf(-z));
    w[e] = ww;
    int d = dst[e];
    atomicAdd(&deg_s[src[e]], ww);
    atomicAdd(&deg_d[d], ww);
    atomicAdd(&cnt[d], 1);
}

__global__ void invsqrt_kernel(float* __restrict__ d, int n) {
    int i = blockIdx.x * blockDim.x + threadIdx.x;
    if (i >= n) return;
    float v = d[i];
    d[i] = (v > 0.f) ? rsqrtf(v) : 0.f;
}

// transpose + fp16-round weights: W[k][n] f32 -> Wt[n][k] fp16
__global__ void prep_w_kernel(const float* __restrict__ W1, const float* __restrict__ W2,
                              __half* __restrict__ W1t, __half* __restrict__ W2t) {
    int i = blockIdx.x * blockDim.x + threadIdx.x;
    int n1 = DFACT * HID;
    if (i < n1) {
        int k = i >> 7, n = i & 127;
        W1t[(size_t)n * DFACT + k] = __float2half_rn(W1[i]);
    } else if (i < n1 + HID * HID) {
        int j = i - n1;
        int k = j >> 7, n = j & 127;
        W2t[(size_t)n * HID + k] = __float2half_rn(W2[j]);
    }
}

// ---------------- CSR build ------------------------------------------------
__global__ void scan_bsum_kernel(const int* __restrict__ cnt, int n, int* __restrict__ bsum) {
    __shared__ int sh[SCAN_BS];
    int i = blockIdx.x * SCAN_BS + threadIdx.x;
    sh[threadIdx.x] = (i < n) ? cnt[i] : 0;
    __syncthreads();
    for (int o = SCAN_BS / 2; o; o >>= 1) {
        if (threadIdx.x < o) sh[threadIdx.x] += sh[threadIdx.x + o];
        __syncthreads();
    }
    if (threadIdx.x == 0) bsum[blockIdx.x] = sh[0];
}

__global__ void scan_tops_kernel(int* __restrict__ bsum, int nb,
                                 int* __restrict__ rowptr, int n) {
    __shared__ int sh[1024];
    int tid = threadIdx.x;
    int v = (tid < nb) ? bsum[tid] : 0;
    sh[tid] = v;
    __syncthreads();
    for (int o = 1; o < 1024; o <<= 1) {
        int t = (tid >= o) ? sh[tid - o] : 0;
        __syncthreads();
        sh[tid] += t;
        __syncthreads();
    }
    if (tid < nb) bsum[tid] = sh[tid] - v;
    if (tid == 0) rowptr[n] = sh[1023];
}

__global__ void scan_write_kernel(const int* __restrict__ cnt, const int* __restrict__ bsum,
                                  int n, int* __restrict__ rowptr, int* __restrict__ cur) {
    __shared__ int sh[SCAN_BS];
    int tid = threadIdx.x;
    int i = blockIdx.x * SCAN_BS + tid;
    int v = (i < n) ? cnt[i] : 0;
    sh[tid] = v;
    __syncthreads();
    for (int o = 1; o < SCAN_BS; o <<= 1) {
        int t = (tid >= o) ? sh[tid - o] : 0;
        __syncthreads();
        sh[tid] += t;
        __syncthreads();
    }
    if (i < n) {
        int ex = sh[tid] - v + bsum[blockIdx.x];
        rowptr[i] = ex;
        cur[i] = ex;
    }
}

__global__ void scatter_kernel(const int* __restrict__ src, const int* __restrict__ dst,
                               const float* __restrict__ w, const float* __restrict__ dis_s,
                               int* __restrict__ cur, uint2* __restrict__ packed, int E) {
    int e = blockIdx.x * blockDim.x + threadIdx.x;
    if (e >= E) return;
    int d = dst[e];
    int pos = atomicAdd(&cur[d], 1);
    int s = src[e];
    packed[pos] = make_uint2((uint32_t)s, __float_as_uint(w[e] * dis_s[s]));
}

// gather: one warp per dst node; out[node] = dis_d[node] * sum_e w'*h[src] (h fp16)
template <bool HOUT>
__global__ void gather_kernel(void* __restrict__ outv, const __half* __restrict__ h,
                              const uint2* __restrict__ packed,
                              const int* __restrict__ rowptr,
                              const float* __restrict__ dis_d, int n) {
    int node = blockIdx.x * (blockDim.x >> 5) + (threadIdx.x >> 5);
    if (node >= n) return;
    int lane = threadIdx.x & 31;
    int r0 = __ldg(rowptr + node), r1 = __ldg(rowptr + node + 1);
    float4 acc = make_float4(0.f, 0.f, 0.f, 0.f);
    for (int base = r0; base < r1; base += 32) {
        int nit = min(32, r1 - base);
        uint2 meta = (lane < nit) ? __ldg(packed + base + lane) : make_uint2(0u, 0u);
        for (int j = 0; j < nit; j++) {
            int   s  = __shfl_sync(0xffffffffu, (int)meta.x, j);
            float wv = __uint_as_float(__shfl_sync(0xffffffffu, meta.y, j));
            uint2 hv = *reinterpret_cast<const uint2*>(h + (size_t)s * 128 + lane * 4);
            __half2 p0 = *reinterpret_cast<__half2*>(&hv.x);
            __half2 p1 = *reinterpret_cast<__half2*>(&hv.y);
            float2 f0 = __half22float2(p0), f1 = __half22float2(p1);
            acc.x += wv * f0.x; acc.y += wv * f0.y;
            acc.z += wv * f1.x; acc.w += wv * f1.y;
        }
    }
    float dd = __ldg(dis_d + node);
    acc.x *= dd; acc.y *= dd; acc.z *= dd; acc.w *= dd;
    if (HOUT) {
        __half* out = (__half*)outv;
        __half2 o0 = __floats2half2_rn(acc.x, acc.y);
        __half2 o1 = __floats2half2_rn(acc.z, acc.w);
        *reinterpret_cast<uint2*>(out + (size_t)node * 128 + lane * 4) =
            make_uint2(*reinterpret_cast<uint32_t*>(&o0), *reinterpret_cast<uint32_t*>(&o1));
    } else {
        reinterpret_cast<float4*>((float*)outv + (size_t)node * 128)[lane] = acc;
    }
}

// ---------------- fp16 tensor-core GEMM ------------------------------------
// C[M,128](fp16) = act(A[M,K] f32) @ Bt[n][k](fp16);  act = relu(x+abias[k]) if HASBIAS
// BM=128, BN=128, BK=32, 256 thr, warp tile 32x64, m16n8k16, double-buffered.
template <bool HASBIAS>
__global__ __launch_bounds__(256) void hgemm128_kernel(
        const float* __restrict__ A, const __half* __restrict__ Bt,
        const float* __restrict__ abias, __half* __restrict__ C,
        int M, int K) {
    __shared__ __half Asm[2][STGH];
    __shared__ __half Bsm[2][STGH];

    const int tid  = threadIdx.x;
    const int wid  = tid >> 5;
    const int lane = tid & 31;
    const int gid  = lane >> 2;
    const int tid4 = lane & 3;
    const int wm   = (wid & 3) * 32;
    const int wn   = (wid >> 2) * 64;
    const int row0 = blockIdx.x * 128;
    const int nt   = K >> 5;

    float acc[2][8][4] = {};

    int aR[4]; const int aC = (tid & 7) * 4;     // A: 4 float4 per thread
    int bR[2]; const int bK = (tid & 3) * 8;     // B: 2 x 16B cp.async per thread
#pragma unroll
    for (int i = 0; i < 4; i++) aR[i] = (tid + i * 256) >> 3;
#pragma unroll
    for (int i = 0; i < 2; i++) bR[i] = (tid + i * 256) >> 2;

    float4 av[4];

#define G_LDG(t)                                                               \
    do {                                                                       \
        int k0 = (t) * 32;                                                     \
        _Pragma("unroll")                                                      \
        for (int i = 0; i < 4; i++) {                                          \
            int r = row0 + aR[i];                                              \
            av[i] = (r < M) ? *reinterpret_cast<const float4*>(                \
                                  A + (size_t)r * K + k0 + aC)                 \
                            : make_float4(0.f, 0.f, 0.f, 0.f);                 \
        }                                                                      \
    } while (0)

#define G_CPB(t)                                                               \
    do {                                                                       \
        int k0 = (t) * 32;                                                     \
        _Pragma("unroll")                                                      \
        for (int i = 0; i < 2; i++) {                                          \
            const __half* gp = Bt + (size_t)bR[i] * K + k0 + bK;               \
            uint32_t sa = (uint32_t)__cvta_generic_to_shared(                  \
                &Bsm[(t) & 1][bR[i] * PITCH + bK]);                            \
            asm volatile("cp.async.cg.shared.global [%0], [%1], 16;"           \
                         :: "r"(sa), "l"(gp));                                 \
        }                                                                      \
    } while (0)

#define G_STS(t)                                                               \
    do {                                                                       \
        int k0 = (t) * 32;                                                     \
        _Pragma("unroll")                                                      \
        for (int i = 0; i < 4; i++) {                                          \
            float4 v = av[i];                                                  \
            if (HASBIAS) {                                                     \
                v.x = fmaxf(v.x + __ldg(abias + k0 + aC + 0), 0.f);            \
                v.y = fmaxf(v.y + __ldg(abias + k0 + aC + 1), 0.f);            \
                v.z = fmaxf(v.z + __ldg(abias + k0 + aC + 2), 0.f);            \
                v.w = fmaxf(v.w + __ldg(abias + k0 + aC + 3), 0.f);            \
            }                                                                  \
            __half2 h0 = __floats2half2_rn(v.x, v.y);                          \
            __half2 h1 = __floats2half2_rn(v.z, v.w);                          \
            *reinterpret_cast<uint2*>(&Asm[(t) & 1][aR[i] * PITCH + aC]) =     \
                make_uint2(*reinterpret_cast<uint32_t*>(&h0),                  \
                           *reinterpret_cast<uint32_t*>(&h1));                 \
        }                                                                      \
    } while (0)

    G_LDG(0);
    G_CPB(0);
    CP_COMMIT();

    for (int t = 0; t < nt; t++) {
        G_STS(t);
        if (t + 1 < nt) { G_LDG(t + 1); G_CPB(t + 1); }
        CP_COMMIT();
        CP_WAIT1();
        __syncthreads();

        const __half* as = Asm[t & 1];
        const __half* bs = Bsm[t & 1];
#pragma unroll
        for (int kk = 0; kk < 32; kk += 16) {
            uint32_t afr[2][4], bfr[8][2];
#pragma unroll
            for (int mi = 0; mi < 2; mi++) {
                int r = wm + mi * 16 + gid;
                afr[mi][0] = *reinterpret_cast<const uint32_t*>(&as[r * PITCH + kk + 2 * tid4]);
                afr[mi][1] = *reinterpret_cast<const uint32_t*>(&as[(r + 8) * PITCH + kk + 2 * tid4]);
                afr[mi][2] = *reinterpret_cast<const uint32_t*>(&as[r * PITCH + kk + 8 + 2 * tid4]);
                afr[mi][3] = *reinterpret_cast<const uint32_t*>(&as[(r + 8) * PITCH + kk + 8 + 2 * tid4]);
            }
#pragma unroll
            for (int ni = 0; ni < 8; ni++) {
                int c = wn + ni * 8 + gid;
                bfr[ni][0] = *reinterpret_cast<const uint32_t*>(&bs[c * PITCH + kk + 2 * tid4]);
                bfr[ni][1] = *reinterpret_cast<const uint32_t*>(&bs[c * PITCH + kk + 8 + 2 * tid4]);
            }
#pragma unroll
            for (int mi = 0; mi < 2; mi++)
#pragma unroll
                for (int ni = 0; ni < 8; ni++)
                    mma_f16(acc[mi][ni], afr[mi], bfr[ni]);
        }
        __syncthreads();
    }

#pragma unroll
    for (int mi = 0; mi < 2; mi++)
#pragma unroll
        for (int ni = 0; ni < 8; ni++) {
            int r1 = row0 + wm + mi * 16 + gid;
            int r2 = r1 + 8;
            int c  = wn + ni * 8 + tid4 * 2;
            if (r1 < M)
                *reinterpret_cast<__half2*>(C + (size_t)r1 * 128 + c) =
                    __floats2half2_rn(acc[mi][ni][0], acc[mi][ni][1]);
            if (r2 < M)
                *reinterpret_cast<__half2*>(C + (size_t)r2 * 128 + c) =
                    __floats2half2_rn(acc[mi][ni][2], acc[mi][ni][3]);
        }
#undef G_LDG
#undef G_CPB
#undef G_STS
}

// fused: relu(f2+b2) . Wc per fact node, atomically pooled per graph (f2 fp16)
__global__ void pool_kernel(const __half* __restrict__ f2,
                            const float* __restrict__ b2,
                            const float* __restrict__ Wc,
                            const int* __restrict__ batch,
                            float* __restrict__ psum,
                            float* __restrict__ pcnt, int n) {
    int node = blockIdx.x * (blockDim.x >> 5) + (threadIdx.x >> 5);
    if (node >= n) return;
    int lane = threadIdx.x & 31;
    uint2 hv = *reinterpret_cast<const uint2*>(f2 + (size_t)node * 128 + lane * 4);
    __half2 p0 = *reinterpret_cast<__half2*>(&hv.x);
    __half2 p1 = *reinterpret_cast<__half2*>(&hv.y);
    float2 f0 = __half22float2(p0), f1 = __half22float2(p1);
    float4 bb = reinterpret_cast<const float4*>(b2)[lane];
    float4 wc = reinterpret_cast<const float4*>(Wc)[lane];
    float s = fmaxf(f0.x + bb.x, 0.f) * wc.x + fmaxf(f0.y + bb.y, 0.f) * wc.y +
              fmaxf(f1.x + bb.z, 0.f) * wc.z + fmaxf(f1.y + bb.w, 0.f) * wc.w;
#pragma unroll
    for (int o = 16; o; o >>= 1) s += __shfl_down_sync(0xffffffffu, s, o);
    if (lane == 0) {
        int g = batch[node];
        atomicAdd(&psum[g], s);
        atomicAdd(&pcnt[g], 1.f);
    }
}

__global__ void final_kernel(const float* __restrict__ psum,
                             const float* __restrict__ pcnt,
                             const float* __restrict__ bc,
                             float* __restrict__ out) {
    int g = threadIdx.x;
    if (g < NB) out[g] = psum[g] / fmaxf(pcnt[g], 1.f) + bc[0];
}

// ---------------- launch ---------------------------------------------------
extern "C" void kernel_launch(void* const* d_in, const int* in_sizes, int n_in,
                              void* d_out, int out_size) {
    const float* x_fact     = (const float*)d_in[0];
    const float* ea_fc      = (const float*)d_in[2];
    const float* ea_cf      = (const float*)d_in[3];
    const int*   fc_src     = (const int*)d_in[4];
    const int*   fc_dst     = (const int*)d_in[5];
    const int*   cf_src     = (const int*)d_in[6];
    const int*   cf_dst     = (const int*)d_in[7];
    const int*   batch_fact = (const int*)d_in[8];
    const float* Wm         = (const float*)d_in[9];
    const float* bm         = (const float*)d_in[10];
    const float* W1_fc      = (const float*)d_in[11];
    const float* b1_fc      = (const float*)d_in[12];
    const float* W2_cf      = (const float*)d_in[17];
    const float* b2_cf      = (const float*)d_in[18];
    const float* Wc         = (const float*)d_in[19];
    const float* bc         = (const float*)d_in[20];
    float* out = (float*)d_out;

    float *wfc, *wcf, *dfcs, *dfcd, *dcfs, *dcfd, *c1, *psum, *pcnt;
    __half *W1t, *W2t, *H1, *H2, *f2;
    int *cntc, *cntf, *bsum, *rpc, *rpf, *curc, *curf;
    uint2 *pfc, *pcf;
    cudaGetSymbolAddress((void**)&wfc,  g_wfc);
    cudaGetSymbolAddress((void**)&wcf,  g_wcf);
    cudaGetSymbolAddress((void**)&dfcs, g_dfc_s);
    cudaGetSymbolAddress((void**)&dfcd, g_dfc_d);
    cudaGetSymbolAddress((void**)&dcfs, g_dcf_s);
    cudaGetSymbolAddress((void**)&dcfd, g_dcf_d);
    cudaGetSymbolAddress((void**)&W1t,  g_W1t);
    cudaGetSymbolAddress((void**)&W2t,  g_W2t);
    cudaGetSymbolAddress((void**)&H1,   g_H1);
    cudaGetSymbolAddress((void**)&c1,   g_c1);
    cudaGetSymbolAddress((void**)&H2,   g_H2);
    cudaGetSymbolAddress((void**)&f2,   g_f2);
    cudaGetSymbolAddress((void**)&psum, g_psum);
    cudaGetSymbolAddress((void**)&pcnt, g_pcnt);
    cudaGetSymbolAddress((void**)&cntc, g_cntc);
    cudaGetSymbolAddress((void**)&cntf, g_cntf);
    cudaGetSymbolAddress((void**)&bsum, g_bsum);
    cudaGetSymbolAddress((void**)&rpc,  g_rpc);
    cudaGetSymbolAddress((void**)&rpf,  g_rpf);
    cudaGetSymbolAddress((void**)&curc, g_curc);
    cudaGetSymbolAddress((void**)&curf, g_curf);
    cudaGetSymbolAddress((void**)&pfc,  g_pfc);
    cudaGetSymbolAddress((void**)&pcf,  g_pcf);

    cudaMemsetAsync(dfcs, 0, NFACT * sizeof(float));
    cudaMemsetAsync(dfcd, 0, NCOMP * sizeof(float));
    cudaMemsetAsync(dcfs, 0, NCOMP * sizeof(float));
    cudaMemsetAsync(dcfd, 0, NFACT * sizeof(float));
    cudaMemsetAsync(cntc, 0, NCOMP * sizeof(int));
    cudaMemsetAsync(cntf, 0, NFACT * sizeof(int));
    cudaMemsetAsync(psum, 0, NB * sizeof(float));
    cudaMemsetAsync(pcnt, 0, NB * sizeof(float));

    const int nbC = (NCOMP + SCAN_BS - 1) / SCAN_BS;
    const int nbF = (NFACT + SCAN_BS - 1) / SCAN_BS;

    // 1,2: edge gates + degrees + CSR histograms (fused)
    gate_deg_kernel<<<(NEDGE + 255) / 256, 256>>>(ea_fc, fc_src, fc_dst, Wm, bm,
                                                  wfc, dfcs, dfcd, cntc, NEDGE);
    gate_deg_kernel<<<(NEDGE + 255) / 256, 256>>>(ea_cf, cf_src, cf_dst, Wm, bm,
                                                  wcf, dcfs, dcfd, cntf, NEDGE);
    // 3: transpose + fp16-round weights
    prep_w_kernel<<<(DFACT * HID + HID * HID + 255) / 256, 256>>>(W1_fc, W2_cf, W1t, W2t);
    // 4: GEMM1 — profiled slot
    hgemm128_kernel<false><<<(NFACT + 127) / 128, 256>>>(x_fact, W1t, nullptr,
                                                         H1, NFACT, DFACT);
    // 5-8: inv-sqrt degrees
    invsqrt_kernel<<<(NFACT + 255) / 256, 256>>>(dfcs, NFACT);
    invsqrt_kernel<<<(NCOMP + 255) / 256, 256>>>(dfcd, NCOMP);
    invsqrt_kernel<<<(NCOMP + 255) / 256, 256>>>(dcfs, NCOMP);
    invsqrt_kernel<<<(NFACT + 255) / 256, 256>>>(dcfd, NFACT);

    // CSR build fc (dst = companies)
    scan_bsum_kernel<<<nbC, SCAN_BS>>>(cntc, NCOMP, bsum);
    scan_tops_kernel<<<1, 1024>>>(bsum, nbC, rpc, NCOMP);
    scan_write_kernel<<<nbC, SCAN_BS>>>(cntc, bsum, NCOMP, rpc, curc);
    scatter_kernel<<<(NEDGE + 255) / 256, 256>>>(fc_src, fc_dst, wfc, dfcs,
                                                 curc, pfc, NEDGE);
    // CSR build cf (dst = facts)
    scan_bsum_kernel<<<nbF, SCAN_BS>>>(cntf, NFACT, bsum);
    scan_tops_kernel<<<1, 1024>>>(bsum, nbF, rpf, NFACT);
    scan_write_kernel<<<nbF, SCAN_BS>>>(cntf, bsum, NFACT, rpf, curf);
    scatter_kernel<<<(NEDGE + 255) / 256, 256>>>(cf_src, cf_dst, wcf, dcfs,
                                                 curf, pcf, NEDGE);

    // gather layer-1 -> c1 (f32, pre-activation)
    gather_kernel<false><<<(NCOMP + 7) / 8, 256>>>((void*)c1, H1, pfc, rpc, dfcd, NCOMP);
    // GEMM2 with fused relu(c1 + b1_fc), fp16 out
    hgemm128_kernel<true><<<(NCOMP + 127) / 128, 256>>>(c1, W2t, b1_fc, H2, NCOMP, HID);
    // gather layer-2 -> f2 (fp16)
    gather_kernel<true><<<(NFACT + 7) / 8, 256>>>((void*)f2, H2, pcf, rpf, dcfd, NFACT);

    // fused relu+bias+classifier-dot+mean-pool
    pool_kernel<<<(NFACT + 7) / 8, 256>>>(f2, b2_cf, Wc, batch_fact,
                                          psum, pcnt, NFACT);
    final_kernel<<<1, NB>>>(psum, pcnt, bc, out);
}